// round 2
// baseline (speedup 1.0000x reference)
#include <cuda_runtime.h>
#include <cstdint>

// Problem constants (fixed by the reference: T=8, x shape [T*32, 128, 32, 32])
#define T_STEPS   8
#define BATCH     32
#define CHANNELS  128
#define HW        1024                      // 32*32
#define N_ELEM    (BATCH*CHANNELS*HW)       // 4,194,304 spatial positions
#define NUM_SLABS (N_ELEM/HW)               // 4096 (b,c) channel-slabs
#define GRID1     1024                      // single balanced wave; 4 slabs/block
#define SLABS_PER_BLOCK 4                   // slabs b, b+1024, b+2048, b+3072 share channel b%128

// Scratch (static device globals — no runtime allocation permitted)
__device__ uint8_t g_spikes[N_ELEM];        // 8 spike bits per position, 4 MiB
__device__ float   g_partials[GRID1];       // per-block sum of new_thre (channel = bid%128)
__device__ float   g_scale;                 // final scalar thre + update

// Block-wide deterministic sum: warp shuffle tree + one smem hop.
__device__ __forceinline__ float block_sum_256(float v) {
    __shared__ float ws[8];
#pragma unroll
    for (int off = 16; off > 0; off >>= 1)
        v += __shfl_down_sync(0xFFFFFFFFu, v, off);
    const int wid = threadIdx.x >> 5;
    if ((threadIdx.x & 31) == 0) ws[wid] = v;
    __syncthreads();
    if (wid == 0) {
        v = (threadIdx.x < 8) ? ws[threadIdx.x] : 0.0f;
#pragma unroll
        for (int off = 4; off > 0; off >>= 1)
            v += __shfl_down_sync(0xFFFFFFFFu, v, off);
    }
    return v;  // valid in thread 0
}

// ---------------------------------------------------------------------------
// Phase 1: IF recurrence + spike-bit pack + per-block new_thre partial sums.
// 1024 blocks (one wave at occ 8), each handling 4 same-channel slabs.
// ---------------------------------------------------------------------------
__global__ __launch_bounds__(256, 8) void if_phase1(const float* __restrict__ x,
                                                    const float* __restrict__ thresh) {
    const float thre = __ldg(thresh);
    float local = 0.0f;

#pragma unroll 1
    for (int k = 0; k < SLABS_PER_BLOCK; k++) {
        const int slab = blockIdx.x + k * GRID1;
        const int n    = slab * HW + threadIdx.x * 4;

        // Hoist the 8 independent timestep loads.
        float4 xv[T_STEPS];
#pragma unroll
        for (int t = 0; t < T_STEPS; t++)
            xv[t] = *reinterpret_cast<const float4*>(x + (size_t)t * N_ELEM + n);

        float    mem[4] = {0.5f * thre, 0.5f * thre, 0.5f * thre, 0.5f * thre};
        unsigned sb[4]  = {0u, 0u, 0u, 0u};

#pragma unroll
        for (int t = 0; t < T_STEPS; t++) {
            const float v[4] = {xv[t].x, xv[t].y, xv[t].z, xv[t].w};
#pragma unroll
            for (int j = 0; j < 4; j++) {
                mem[j] += v[j];
                if (mem[j] >= thre) {      // heaviside(mem - cur)
                    mem[j] -= thre;        // mem -= s*cur
                    sb[j]  |= (1u << t);
                }
            }
        }

        *reinterpret_cast<uchar4*>(g_spikes + n) =
            make_uchar4((unsigned char)sb[0], (unsigned char)sb[1],
                        (unsigned char)sb[2], (unsigned char)sb[3]);

        // Compensation pass -> per-element new_thre (cnt via popc).
#pragma unroll
        for (int j = 0; j < 4; j++) {
            const int   cnt = __popc(sb[j]);
            const float cv  = fminf((mem[j] - 0.5f * thre) + (float)cnt * thre,
                                    (float)T_STEPS * thre);
            if (cv > 0.0f && cnt > 0)
                local += cv / (float)cnt;
        }
    }

    const float total = block_sum_256(local);
    if (threadIdx.x == 0) g_partials[blockIdx.x] = total;
}

// ---------------------------------------------------------------------------
// Phase 2: per-channel ub (8 partials each), masked mean -> scalar scale.
// ---------------------------------------------------------------------------
__global__ __launch_bounds__(128) void if_phase2(const float* __restrict__ thresh) {
    const float thre = __ldg(thresh);
    const int   c    = threadIdx.x;       // channel

    float s = 0.0f;
#pragma unroll
    for (int k = 0; k < GRID1 / CHANNELS; k++)     // 8 blocks per channel
        s += g_partials[c + k * CHANNELS];
    const float ub      = s / (float)(BATCH * HW);             // mean over (B,H,W)
    const float contrib = (thre > ub) ? (ub - thre) : 0.0f;    // diff * mask

    __shared__ float red[128];
    red[c] = contrib;
    __syncthreads();
#pragma unroll
    for (int st = 64; st > 0; st >>= 1) {
        if (c < st) red[c] += red[c + st];
        __syncthreads();
    }
    if (c == 0)
        g_scale = thre + 0.2f * red[0] / (float)CHANNELS;      // LR*2 = 0.2
}

// ---------------------------------------------------------------------------
// Phase 3: expand spike bits * scalar scale to the full [T*B,C,H,W] output.
// Same 1024-block single-wave layout as phase1.
// ---------------------------------------------------------------------------
__global__ __launch_bounds__(256, 8) void if_phase3(float* __restrict__ out) {
    const float scale = g_scale;

#pragma unroll 1
    for (int k = 0; k < SLABS_PER_BLOCK; k++) {
        const int slab = blockIdx.x + k * GRID1;
        const int n    = slab * HW + threadIdx.x * 4;
        const uchar4 sb = *reinterpret_cast<const uchar4*>(g_spikes + n);

#pragma unroll
        for (int t = 0; t < T_STEPS; t++) {
            float4 o;
            o.x = ((sb.x >> t) & 1) ? scale : 0.0f;
            o.y = ((sb.y >> t) & 1) ? scale : 0.0f;
            o.z = ((sb.z >> t) & 1) ? scale : 0.0f;
            o.w = ((sb.w >> t) & 1) ? scale : 0.0f;
            *reinterpret_cast<float4*>(out + (size_t)t * N_ELEM + n) = o;
        }
    }
}

// ---------------------------------------------------------------------------
extern "C" void kernel_launch(void* const* d_in, const int* in_sizes, int n_in,
                              void* d_out, int out_size) {
    const float* x      = (const float*)d_in[0];   // [T*B, C, H, W] fp32
    const float* thresh = (const float*)d_in[1];   // [1] fp32
    float*       out    = (float*)d_out;

    if_phase1<<<GRID1, 256>>>(x, thresh);
    if_phase2<<<1, 128>>>(thresh);
    if_phase3<<<GRID1, 256>>>(out);
}

// round 3
// speedup vs baseline: 1.0503x; 1.0503x over previous
#include <cuda_runtime.h>
#include <cstdint>

// Problem constants (fixed by the reference: T=8, x shape [T*32, 128, 32, 32])
#define T_STEPS   8
#define BATCH     32
#define CHANNELS  128
#define HW        1024                      // 32*32
#define N_ELEM    (BATCH*CHANNELS*HW)       // 4,194,304 spatial positions
#define GRID1     1024                      // single wave; all blocks co-resident
#define SLABS_PER_BLOCK 4                   // slabs b, b+1024, b+2048, b+3072 share channel b%128

// Scratch (static device globals — no runtime allocation permitted).
// Barrier counters are MONOTONIC across graph replays (each replay consumes
// exactly GRID1 arrivals) -> no reset needed, fully deterministic.
__device__ float    g_partials[GRID1];
__device__ float    g_scale;
__device__ unsigned g_arrive  = 0;
__device__ unsigned g_release = 0;

// Block-wide deterministic sum: warp shuffle tree + one smem hop.
// (Caller guarantees a __syncthreads() between successive uses.)
__device__ __forceinline__ float block_sum_256(float v) {
    __shared__ float ws[8];
#pragma unroll
    for (int off = 16; off > 0; off >>= 1)
        v += __shfl_down_sync(0xFFFFFFFFu, v, off);
    const int wid = threadIdx.x >> 5;
    if ((threadIdx.x & 31) == 0) ws[wid] = v;
    __syncthreads();
    if (wid == 0) {
        v = (threadIdx.x < 8) ? ws[threadIdx.x] : 0.0f;
#pragma unroll
        for (int off = 4; off > 0; off >>= 1)
            v += __shfl_down_sync(0xFFFFFFFFu, v, off);
    }
    return v;  // valid in thread 0
}

// ---------------------------------------------------------------------------
// Fused persistent kernel: IF recurrence -> grid barrier -> scaled expansion.
// 1024 blocks, all resident (148 SMs x 7 blocks >= 1024) -> spin is safe.
// ---------------------------------------------------------------------------
__global__ __launch_bounds__(256, 7) void if_fused(const float* __restrict__ x,
                                                   const float* __restrict__ thresh,
                                                   float* __restrict__ out) {
    __shared__ uint32_t s_bits[SLABS_PER_BLOCK][256];   // packed spike bytes, 4 KiB
    __shared__ float    s_scale;
    __shared__ unsigned s_gen;
    __shared__ int      s_last;

    const float thre = __ldg(thresh);
    float local = 0.0f;

    // ---- Phase A: recurrence over 4 same-channel slabs ----
#pragma unroll 1
    for (int k = 0; k < SLABS_PER_BLOCK; k++) {
        const int slab = blockIdx.x + k * GRID1;
        const int n    = slab * HW + threadIdx.x * 4;

        float4 xv[T_STEPS];
#pragma unroll
        for (int t = 0; t < T_STEPS; t++)
            xv[t] = *reinterpret_cast<const float4*>(x + (size_t)t * N_ELEM + n);

        float    mem[4] = {0.5f * thre, 0.5f * thre, 0.5f * thre, 0.5f * thre};
        unsigned sb[4]  = {0u, 0u, 0u, 0u};

#pragma unroll
        for (int t = 0; t < T_STEPS; t++) {
            const float v[4] = {xv[t].x, xv[t].y, xv[t].z, xv[t].w};
#pragma unroll
            for (int j = 0; j < 4; j++) {
                mem[j] += v[j];
                if (mem[j] >= thre) {          // heaviside(mem - cur)
                    mem[j] -= thre;            // mem -= s*cur
                    sb[j]  |= (1u << t);
                }
            }
        }

        s_bits[k][threadIdx.x] = sb[0] | (sb[1] << 8) | (sb[2] << 16) | (sb[3] << 24);

        // Compensation pass -> per-element new_thre (cnt via popc).
#pragma unroll
        for (int j = 0; j < 4; j++) {
            const int   cnt = __popc(sb[j]);
            const float cv  = fminf((mem[j] - 0.5f * thre) + (float)cnt * thre,
                                    (float)T_STEPS * thre);
            if (cv > 0.0f && cnt > 0)
                local += cv / (float)cnt;
        }
    }

    const float total = block_sum_256(local);

    // ---- Grid barrier (generation-counted, monotonic across replays) ----
    if (threadIdx.x == 0) {
        g_partials[blockIdx.x] = total;
        __threadfence();
        const unsigned old = atomicAdd(&g_arrive, 1u);
        s_gen  = old / GRID1;                    // replay index
        s_last = ((old % GRID1) == GRID1 - 1);   // last arriver finalizes
    }
    __syncthreads();

    if (s_last) {
        // Per-channel ub from 8 partials each (channel = partial_idx % 128),
        // masked diff, deterministic fixed-order reduction.
        float contrib = 0.0f;
        if (threadIdx.x < CHANNELS) {
            float s = 0.0f;
#pragma unroll
            for (int kk = 0; kk < GRID1 / CHANNELS; kk++)
                s += g_partials[threadIdx.x + kk * CHANNELS];
            const float ub = s / (float)(BATCH * HW);
            contrib = (thre > ub) ? (ub - thre) : 0.0f;
        }
        const float tot = block_sum_256(contrib);
        if (threadIdx.x == 0) {
            g_scale = thre + 0.2f * tot / (float)CHANNELS;   // LR*2 = 0.2
            __threadfence();
            atomicAdd(&g_release, 1u);
        }
    }

    if (threadIdx.x == 0) {
        const unsigned target = s_gen + 1u;
        unsigned v;
        do {
            asm volatile("ld.acquire.gpu.u32 %0, [%1];" : "=r"(v) : "l"(&g_release));
        } while (v < target);
        s_scale = g_scale;
    }
    __syncthreads();

    // ---- Phase B: expand spike bits * scalar to output ----
    const float scale = s_scale;
#pragma unroll 1
    for (int k = 0; k < SLABS_PER_BLOCK; k++) {
        const int      slab = blockIdx.x + k * GRID1;
        const int      n    = slab * HW + threadIdx.x * 4;
        const uint32_t bits = s_bits[k][threadIdx.x];

#pragma unroll
        for (int t = 0; t < T_STEPS; t++) {
            float4 o;
            o.x = ((bits >> (t))      & 1u) ? scale : 0.0f;
            o.y = ((bits >> (t + 8))  & 1u) ? scale : 0.0f;
            o.z = ((bits >> (t + 16)) & 1u) ? scale : 0.0f;
            o.w = ((bits >> (t + 24)) & 1u) ? scale : 0.0f;
            *reinterpret_cast<float4*>(out + (size_t)t * N_ELEM + n) = o;
        }
    }
}

// ---------------------------------------------------------------------------
extern "C" void kernel_launch(void* const* d_in, const int* in_sizes, int n_in,
                              void* d_out, int out_size) {
    const float* x      = (const float*)d_in[0];   // [T*B, C, H, W] fp32
    const float* thresh = (const float*)d_in[1];   // [1] fp32
    float*       out    = (float*)d_out;

    if_fused<<<GRID1, 256>>>(x, thresh, out);
}